// round 1
// baseline (speedup 1.0000x reference)
#include <cuda_runtime.h>
#include <math.h>

// Problem constants (match reference)
#define T_STEPS 1024
#define B_SIZE  32768
#define G1      50
#define H1      32
#define G2      20

// Scratch for betas (device global — no allocation allowed)
__device__ float g_betas[T_STEPS];

// ---------------------------------------------------------------------------
// Kernel 1: compute beta[t] = softplus(KAN2(KAN1(t/T))) — one block per t.
// 64 threads/block. Layer-1 RBF basis (50 exps) shared in smem; layer-2 is a
// 640-term block reduction.
// ---------------------------------------------------------------------------
__global__ void kan_beta_kernel(const float* __restrict__ t_steps,
                                const float* __restrict__ grid1,
                                const float* __restrict__ spline_w1, // [50,32]
                                const float* __restrict__ base_w1,   // [32]
                                const float* __restrict__ grid2,
                                const float* __restrict__ spline_w2, // [640]
                                const float* __restrict__ base_w2)   // [32]
{
    __shared__ float basis1[G1];
    __shared__ float hsm[H1];
    __shared__ float warpsum[2];

    const int t   = blockIdx.x;
    const int tid = threadIdx.x;
    const float x = t_steps[t];  // t_steps is [T,1]

    // Layer 1 RBF basis: exp(-10*(x-g)^2), shared across the 32 outputs
    if (tid < G1) {
        float d = x - grid1[tid];
        basis1[tid] = __expf(-10.0f * d * d);
    }
    __syncthreads();

    // h[j] = x*base_w1[j] + sum_g basis1[g]*spline_w1[g*32+j]
    if (tid < H1) {
        float acc = x * base_w1[tid];
        #pragma unroll
        for (int g = 0; g < G1; g++) {
            acc = fmaf(basis1[g], spline_w1[g * H1 + tid], acc);
        }
        hsm[tid] = acc;
    }
    __syncthreads();

    // Layer 2: out = sum_i h[i]*base_w2[i] + sum_{i,g} exp(-10*(h[i]-grid2[g])^2)*w2[i*20+g]
    float acc = 0.0f;
    #pragma unroll
    for (int k = 0; k < (H1 * G2) / 64; k++) {   // 640/64 = 10 iterations
        int idx = tid + k * 64;
        int i = idx / G2;
        int g = idx - i * G2;
        float d = hsm[i] - grid2[g];
        acc = fmaf(__expf(-10.0f * d * d), spline_w2[idx], acc);
    }
    if (tid < H1) acc = fmaf(hsm[tid], base_w2[tid], acc);

    // Block reduce 64 -> 1
    #pragma unroll
    for (int o = 16; o > 0; o >>= 1)
        acc += __shfl_down_sync(0xFFFFFFFFu, acc, o);
    if ((tid & 31) == 0) warpsum[tid >> 5] = acc;
    __syncthreads();
    if (tid == 0) {
        float v = warpsum[0] + warpsum[1];
        // stable softplus
        float beta = fmaxf(v, 0.0f) + log1pf(expf(-fabsf(v)));
        g_betas[t] = beta;
    }
}

// ---------------------------------------------------------------------------
// Kernel 2: Euler SIR scan — one thread per batch element, betas in smem.
// out[t*B + b] = I after step t. Coalesced 128B/warp stores.
// ---------------------------------------------------------------------------
__global__ void __launch_bounds__(256, 1)
sir_scan_kernel(const float* __restrict__ initial_I,
                const float* __restrict__ t_steps,
                const float* __restrict__ gamma_param,
                float* __restrict__ out)
{
    __shared__ float sbeta[T_STEPS];
    for (int i = threadIdx.x; i < T_STEPS; i += blockDim.x)
        sbeta[i] = g_betas[i];

    const int b = blockIdx.x * blockDim.x + threadIdx.x;

    float I = initial_I[b];
    float S = 1.0f - I;

    const float gp    = gamma_param[0];
    const float gamma = fmaxf(gp, 0.0f) + log1pf(expf(-fabsf(gp)));
    const float dt    = t_steps[1] - t_steps[0];

    __syncthreads();

    float* outp = out + b;
    #pragma unroll 8
    for (int t = 0; t < T_STEPS; t++) {
        const float beta = sbeta[t];
        const float ni = beta * S * I;                 // new infections
        const float dI = fmaf(-gamma, I, ni);          // ni - gamma*I
        I = fminf(fmaxf(fmaf(dt, dI, I), 0.0f), 5.0f);
        S = fminf(fmaxf(fmaf(-dt, ni, S), 0.0f), 5.0f);
        outp[(size_t)t * B_SIZE] = I;
    }
}

// ---------------------------------------------------------------------------
// Launch. Inputs (metadata order):
// 0: t_steps [1024], 1: initial_I [32768], 2: grid1 [50], 3: spline_w1 [1600],
// 4: base_w1 [32], 5: grid2 [20], 6: spline_w2 [640], 7: base_w2 [32],
// 8: gamma_param [1]
// ---------------------------------------------------------------------------
extern "C" void kernel_launch(void* const* d_in, const int* in_sizes, int n_in,
                              void* d_out, int out_size)
{
    const float* t_steps    = (const float*)d_in[0];
    const float* initial_I  = (const float*)d_in[1];
    const float* grid1      = (const float*)d_in[2];
    const float* spline_w1  = (const float*)d_in[3];
    const float* base_w1    = (const float*)d_in[4];
    const float* grid2      = (const float*)d_in[5];
    const float* spline_w2  = (const float*)d_in[6];
    const float* base_w2    = (const float*)d_in[7];
    const float* gamma_p    = (const float*)d_in[8];
    float* out              = (float*)d_out;

    kan_beta_kernel<<<T_STEPS, 64>>>(t_steps, grid1, spline_w1, base_w1,
                                     grid2, spline_w2, base_w2);
    sir_scan_kernel<<<B_SIZE / 256, 256>>>(initial_I, t_steps, gamma_p, out);
}

// round 2
// speedup vs baseline: 1.0849x; 1.0849x over previous
#include <cuda_runtime.h>
#include <math.h>

// Problem constants (match reference)
#define T_STEPS 1024
#define B_SIZE  32768
#define G1      50
#define H1      32
#define G2      20

// Scratch: dt * beta[t] (device global — no allocation allowed)
__device__ float g_cbeta[T_STEPS];

// ---------------------------------------------------------------------------
// Kernel 1: cbeta[t] = dt * softplus(KAN2(KAN1(t/T))) — one block per t.
// ---------------------------------------------------------------------------
__global__ void kan_beta_kernel(const float* __restrict__ t_steps,
                                const float* __restrict__ grid1,
                                const float* __restrict__ spline_w1, // [50,32]
                                const float* __restrict__ base_w1,   // [32]
                                const float* __restrict__ grid2,
                                const float* __restrict__ spline_w2, // [640]
                                const float* __restrict__ base_w2)   // [32]
{
    __shared__ float basis1[G1];
    __shared__ float hsm[H1];
    __shared__ float warpsum[2];

    const int t   = blockIdx.x;
    const int tid = threadIdx.x;
    const float x = t_steps[t];  // t_steps is [T,1]

    // Layer 1 RBF basis: exp(-10*(x-g)^2), shared across the 32 outputs
    if (tid < G1) {
        float d = x - grid1[tid];
        basis1[tid] = __expf(-10.0f * d * d);
    }
    __syncthreads();

    // h[j] = x*base_w1[j] + sum_g basis1[g]*spline_w1[g*32+j]
    if (tid < H1) {
        float acc = x * base_w1[tid];
        #pragma unroll
        for (int g = 0; g < G1; g++) {
            acc = fmaf(basis1[g], spline_w1[g * H1 + tid], acc);
        }
        hsm[tid] = acc;
    }
    __syncthreads();

    // Layer 2: out = sum_i h[i]*base_w2[i] + sum_{i,g} exp(-10*(h[i]-g2[g])^2)*w2[i*20+g]
    float acc = 0.0f;
    #pragma unroll
    for (int k = 0; k < (H1 * G2) / 64; k++) {   // 640/64 = 10
        int idx = tid + k * 64;
        int i = idx / G2;
        int g = idx - i * G2;
        float d = hsm[i] - grid2[g];
        acc = fmaf(__expf(-10.0f * d * d), spline_w2[idx], acc);
    }
    if (tid < H1) acc = fmaf(hsm[tid], base_w2[tid], acc);

    #pragma unroll
    for (int o = 16; o > 0; o >>= 1)
        acc += __shfl_down_sync(0xFFFFFFFFu, acc, o);
    if ((tid & 31) == 0) warpsum[tid >> 5] = acc;
    __syncthreads();
    if (tid == 0) {
        float v = warpsum[0] + warpsum[1];
        float beta = fmaxf(v, 0.0f) + log1pf(expf(-fabsf(v)));  // stable softplus
        float dt = t_steps[1] - t_steps[0];
        g_cbeta[t] = dt * beta;
    }
}

// ---------------------------------------------------------------------------
// Kernel 2: Euler SIR scan — one thread per batch element.
// 512 blocks x 64 threads: all 32768 threads resident across 148 SMs.
// Per-iter: ni = cb*S*I; I = clip(I*a + ni); S = clip(S - ni); store I.
// ---------------------------------------------------------------------------
__global__ void __launch_bounds__(64)
sir_scan_kernel(const float* __restrict__ initial_I,
                const float* __restrict__ t_steps,
                const float* __restrict__ gamma_param,
                float* __restrict__ out)
{
    __shared__ float scb[T_STEPS];
    #pragma unroll
    for (int i = 0; i < T_STEPS / 64; i++)
        scb[threadIdx.x + i * 64] = g_cbeta[threadIdx.x + i * 64];

    const int b = blockIdx.x * 64 + threadIdx.x;

    float I = initial_I[b];
    float S = 1.0f - I;

    const float gp    = gamma_param[0];
    const float gamma = fmaxf(gp, 0.0f) + log1pf(expf(-fabsf(gp)));
    const float dt    = t_steps[1] - t_steps[0];
    const float a     = 1.0f - dt * gamma;   // I' = I*a + ni

    __syncthreads();

    float* outp = out + b;
    #pragma unroll 16
    for (int t = 0; t < T_STEPS; t++) {
        const float cb = scb[t];
        const float ni = cb * S * I;                      // dt * new_infections
        I = fminf(fmaxf(fmaf(I, a, ni), 0.0f), 5.0f);
        S = fminf(fmaxf(S - ni, 0.0f), 5.0f);
        outp[(size_t)t * B_SIZE] = I;
    }
}

// ---------------------------------------------------------------------------
// Inputs (metadata order):
// 0: t_steps [1024], 1: initial_I [32768], 2: grid1 [50], 3: spline_w1 [1600],
// 4: base_w1 [32], 5: grid2 [20], 6: spline_w2 [640], 7: base_w2 [32],
// 8: gamma_param [1]
// ---------------------------------------------------------------------------
extern "C" void kernel_launch(void* const* d_in, const int* in_sizes, int n_in,
                              void* d_out, int out_size)
{
    const float* t_steps    = (const float*)d_in[0];
    const float* initial_I  = (const float*)d_in[1];
    const float* grid1      = (const float*)d_in[2];
    const float* spline_w1  = (const float*)d_in[3];
    const float* base_w1    = (const float*)d_in[4];
    const float* grid2      = (const float*)d_in[5];
    const float* spline_w2  = (const float*)d_in[6];
    const float* base_w2    = (const float*)d_in[7];
    const float* gamma_p    = (const float*)d_in[8];
    float* out              = (float*)d_out;

    kan_beta_kernel<<<T_STEPS, 64>>>(t_steps, grid1, spline_w1, base_w1,
                                     grid2, spline_w2, base_w2);
    sir_scan_kernel<<<B_SIZE / 64, 64>>>(initial_I, t_steps, gamma_p, out);
}